// round 14
// baseline (speedup 1.0000x reference)
#include <cuda_runtime.h>
#include <cuda_fp16.h>
#include <cstdint>

#define SEQ   4096
#define DM    1024
#define HD    128
#define BATCH 4
#define NQT   32          // SEQ / 128
// SCALE * log2(e): Q is pre-scaled so softmax is p = 2^s
#define QSCALE 0.1275174365f

__device__ __half g_Q[BATCH*SEQ*HD];
__device__ __half g_K[BATCH*SEQ*HD];
__device__ __half g_V[BATCH*SEQ*HD];
__device__ float  g_Op4[4][BATCH*SEQ*HD];
__device__ float  g_lp4[4][BATCH*SEQ];

// ---------------- helpers ----------------
__device__ __forceinline__ uint32_t smem_u32(const void* p) {
    uint32_t a;
    asm("{ .reg .u64 t; cvta.to.shared.u64 t, %1; cvt.u32.u64 %0, t; }" : "=r"(a) : "l"(p));
    return a;
}
__device__ __forceinline__ void ldsm4(uint32_t* r, uint32_t a) {
    asm volatile("ldmatrix.sync.aligned.m8n8.x4.shared.b16 {%0,%1,%2,%3}, [%4];"
        : "=r"(r[0]), "=r"(r[1]), "=r"(r[2]), "=r"(r[3]) : "r"(a));
}
__device__ __forceinline__ void ldsm4t(uint32_t* r, uint32_t a) {
    asm volatile("ldmatrix.sync.aligned.m8n8.x4.trans.shared.b16 {%0,%1,%2,%3}, [%4];"
        : "=r"(r[0]), "=r"(r[1]), "=r"(r[2]), "=r"(r[3]) : "r"(a));
}
__device__ __forceinline__ void mma16(float4& d, const uint32_t a[4], const uint32_t b[2]) {
    asm volatile(
        "mma.sync.aligned.m16n8k16.row.col.f32.f16.f16.f32 "
        "{%0,%1,%2,%3}, {%4,%5,%6,%7}, {%8,%9}, {%0,%1,%2,%3};"
        : "+f"(d.x), "+f"(d.y), "+f"(d.z), "+f"(d.w)
        : "r"(a[0]), "r"(a[1]), "r"(a[2]), "r"(a[3]), "r"(b[0]), "r"(b[1]));
}
__device__ __forceinline__ void cp16(uint32_t s, const void* g) {
    asm volatile("cp.async.cg.shared.global [%0], [%1], 16;" :: "r"(s), "l"(g));
}
#define CP_COMMIT() asm volatile("cp.async.commit_group;" ::: "memory")
template<int N> __device__ __forceinline__ void cp_wait() {
    asm volatile("cp.async.wait_group %0;" :: "n"(N) : "memory");
}
__device__ __forceinline__ uint32_t packh2(float a, float b) {
    __half2 h = __floats2half2_rn(a, b);
    return *(uint32_t*)&h;
}
__device__ __forceinline__ float ex2f(float x) {
    float y;
    asm("ex2.approx.f32 %0, %1;" : "=f"(y) : "f"(x));
    return y;
}
__device__ __forceinline__ uint32_t ex2h2(uint32_t x) {
    uint32_t y;
    asm("ex2.approx.f16x2 %0, %1;" : "=r"(y) : "r"(x));
    return y;
}

// ---------------------------------------------------------------------------
// QKV projection: C[16384,128] = x @ W[wsel], fused fp32->fp16 conversion.
// 256 threads, 8 warps (4m x 2n), warp tile 32x64, K chunk 32,
// register-double-buffered LDG fp32 -> cvt -> STS fp16, 1 sync per chunk.
// A: [128 m][40 k] halfs. B: [32 k][136 n] halfs (ldsmt).
// ---------------------------------------------------------------------------
#define QA_H (128*40)
#define QB_H (32*136)
#define PROJ_SMEM ((2*QA_H + 2*QB_H) * 2)   // 37888 B

__global__ __launch_bounds__(256, 2)
void qkv_mma(const float* __restrict__ x,
             const float* __restrict__ Wq,
             const float* __restrict__ Wk,
             const float* __restrict__ Wv)
{
    extern __shared__ __half smh[];
    const uint32_t a_b = smem_u32(smh);
    const uint32_t b_b = a_b + 2 * QA_H * 2;
    __half* Ah = smh;                      // [2][128][40]
    __half* Bt = smh + 2 * QA_H;           // [2][32][136]

    const int tid  = threadIdx.x;
    const int lane = tid & 31, wid = tid >> 5;
    const int gr = lane >> 2, gc = lane & 3;
    const int wm = wid & 3, wn = wid >> 2;

    const int wsel = blockIdx.y;
    const float* __restrict__ W = (wsel == 0) ? Wq : (wsel == 1) ? Wk : Wv;
    __half* __restrict__ C = (wsel == 0) ? g_Q : (wsel == 1) ? g_K : g_V;
    const float osc = (wsel == 0) ? QSCALE : 1.0f;
    const int m0 = blockIdx.x * 128;

    const int lrow  = ((lane >> 3) & 1) * 8 + (lane & 7);
    const int lcolA = (lane >> 4) * 8;

    // A staging: i = tid + t*256, r = i>>3 (m row), c4 = i&7 (16B seg) — coalesced
    const int ar = tid >> 3, ac = tid & 7;
    // B staging: r = tid>>3 (k row), n0 = (tid&7)*16 — coalesced row segments
    const int br = tid >> 3, bn = (tid & 7) * 16;

    float4 acc[2][8];
    #pragma unroll
    for (int i = 0; i < 2; i++)
        #pragma unroll
        for (int j = 0; j < 8; j++) acc[i][j] = make_float4(0.f, 0.f, 0.f, 0.f);

    float4 ra[4], rw[4];
    auto fetch = [&](int kc) {
        #pragma unroll
        for (int t = 0; t < 4; ++t)   // A: rows ar + t*32
            ra[t] = *(const float4*)&x[(size_t)(m0 + ar + t * 32) * DM + kc * 32 + ac * 4];
        #pragma unroll
        for (int t = 0; t < 4; ++t)   // B: row br of W chunk, cols bn + t*4
            rw[t] = *(const float4*)&W[(size_t)(kc * 32 + br) * HD + bn + t * 4];
    };
    auto store = [&](int bsel) {
        __half* Ad = Ah + bsel * QA_H;
        #pragma unroll
        for (int t = 0; t < 4; ++t) {
            *(__half2*)&Ad[(ar + t * 32) * 40 + ac * 4]     = __floats2half2_rn(ra[t].x, ra[t].y);
            *(__half2*)&Ad[(ar + t * 32) * 40 + ac * 4 + 2] = __floats2half2_rn(ra[t].z, ra[t].w);
        }
        __half* Bd = Bt + bsel * QB_H;
        uint4 v0 = make_uint4(packh2(rw[0].x, rw[0].y), packh2(rw[0].z, rw[0].w),
                              packh2(rw[1].x, rw[1].y), packh2(rw[1].z, rw[1].w));
        uint4 v1 = make_uint4(packh2(rw[2].x, rw[2].y), packh2(rw[2].z, rw[2].w),
                              packh2(rw[3].x, rw[3].y), packh2(rw[3].z, rw[3].w));
        *(uint4*)&Bd[br * 136 + bn]     = v0;
        *(uint4*)&Bd[br * 136 + bn + 8] = v1;
    };

    fetch(0);
    int buf = 0;
    for (int kc = 0; kc < 32; ++kc) {
        store(buf);
        __syncthreads();
        if (kc < 31) fetch(kc + 1);
        uint32_t as = a_b + buf * QA_H * 2;
        uint32_t bs = b_b + buf * QB_H * 2;
        #pragma unroll
        for (int ks = 0; ks < 2; ++ks) {
            const int k0 = ks * 16;
            uint32_t af[2][4];
            ldsm4(af[0], as + (uint32_t)(((wm * 32 + lrow) * 40 + k0 + lcolA) * 2));
            ldsm4(af[1], as + (uint32_t)(((wm * 32 + 16 + lrow) * 40 + k0 + lcolA) * 2));
            #pragma unroll
            for (int p = 0; p < 4; ++p) {
                int n0 = wn * 64 + p * 16;
                uint32_t bf[4];
                ldsm4t(bf, bs + (uint32_t)(((k0 + lrow) * 136 + n0 + lcolA) * 2));
                #pragma unroll
                for (int mf = 0; mf < 2; ++mf) {
                    mma16(acc[mf][2 * p],     af[mf], bf);
                    mma16(acc[mf][2 * p + 1], af[mf], bf + 2);
                }
            }
        }
        buf ^= 1;
    }

    #pragma unroll
    for (int mf = 0; mf < 2; ++mf) {
        size_t r0 = (size_t)(m0 + wm * 32 + mf * 16 + gr);
        #pragma unroll
        for (int nf = 0; nf < 8; ++nf) {
            int col = wn * 64 + nf * 8 + 2 * gc;
            float4 v = acc[mf][nf];
            *(__half2*)&C[r0 * HD + col]       = __floats2half2_rn(v.x * osc, v.y * osc);
            *(__half2*)&C[(r0 + 8) * HD + col] = __floats2half2_rn(v.z * osc, v.w * osc);
        }
    }
}

// ---------------------------------------------------------------------------
// Flash attention: 128 threads, 4 warps x m32 slabs, P in registers,
// p = ex2 (Q pre-scaled; f16x2 MUFU on interior tiles), l via ones-MMA,
// masked-tile skip, cp.async double-buffered K/V, 4-way kv split.
// ---------------------------------------------------------------------------
#define SQ 136
#define NQ_H (128*SQ)
#define NK_H (64*SQ)
#define ATT_SMEM ((NQ_H + 4*NK_H) * 2)    // 104448 B
#define ONESH2 0x3C003C00u

__global__ __launch_bounds__(128, 2)
void attn_mma(void)
{
    extern __shared__ __half smh[];
    const uint32_t qs_b = smem_u32(smh);
    const uint32_t kv_b = qs_b + NQ_H * 2;

    const int tid  = threadIdx.x;
    const int lane = tid & 31, wid = tid >> 5;
    const int gr = lane >> 2, gc = lane & 3;
    const int wr = wid * 32;

    const int qt   = (NQT - 1) - (blockIdx.x >> 2);
    const int part = blockIdx.x & 3;
    const int b    = blockIdx.y;
    const int nkv  = 2 * qt + 2;
    const int kt0  = (nkv * part) >> 2;
    const int kt1  = (nkv * (part + 1)) >> 2;

    const int lrow  = ((lane >> 3) & 1) * 8 + (lane & 7);
    const int lcolA = (lane >> 4) * 8;
    const int brow  = (lane >> 4) * 8 + (lane & 7);
    const int bcol  = ((lane >> 3) & 1) * 8;

    auto issue_kv = [&](int kt, int bsel) {
        uint32_t ks = kv_b + (2 * bsel) * NK_H * 2;
        uint32_t vs = ks + NK_H * 2;
        const __half* Kg = g_K + ((size_t)b * SEQ + kt * 64) * HD;
        const __half* Vg = g_V + ((size_t)b * SEQ + kt * 64) * HD;
        #pragma unroll
        for (int t = 0; t < 8; ++t) {
            int i = tid + t * 128;
            int r = i >> 4, u = i & 15;
            uint32_t so = (uint32_t)((r * SQ + u * 8) * 2);
            cp16(ks + so, Kg + (size_t)r * HD + u * 8);
            cp16(vs + so, Vg + (size_t)r * HD + u * 8);
        }
    };

    {
        const __half* Qg = g_Q + ((size_t)b * SEQ + qt * 128) * HD;
        #pragma unroll
        for (int t = 0; t < 16; ++t) {
            int i = tid + t * 128;
            int r = i >> 4, u = i & 15;
            cp16(qs_b + (uint32_t)((r * SQ + u * 8) * 2), Qg + (size_t)r * HD + u * 8);
        }
        if (kt0 < kt1) issue_kv(kt0, 0);
        CP_COMMIT();
    }

    float4 oacc[2][16];
    float4 lacc[2];
    #pragma unroll
    for (int mf = 0; mf < 2; ++mf) {
        #pragma unroll
        for (int j = 0; j < 16; ++j) oacc[mf][j] = make_float4(0.f, 0.f, 0.f, 0.f);
        lacc[mf] = make_float4(0.f, 0.f, 0.f, 0.f);
    }

    const int rmin = qt * 128 + wr;       // warp's smallest q row
    const int qr0  = rmin + gr;
    const uint32_t ones[2] = { ONESH2, ONESH2 };

    int buf = 0;
    for (int kt = kt0; kt < kt1; ++kt) {
        if (kt + 1 < kt1) { issue_kv(kt + 1, buf ^ 1); CP_COMMIT(); cp_wait<1>(); }
        else              { cp_wait<0>(); }
        __syncthreads();

        if (kt * 64 <= rmin + 31) {       // else: warp fully masked for this tile
            const uint32_t kb = kv_b + (2 * buf) * NK_H * 2;
            const uint32_t vb_base = kb + NK_H * 2;

            // ---- S = Q K^T : m32 x n64, ks-outer (Q frags loaded once) ----
            float4 s[2][8];
            #pragma unroll
            for (int mf = 0; mf < 2; ++mf)
                #pragma unroll
                for (int j = 0; j < 8; ++j) s[mf][j] = make_float4(0.f, 0.f, 0.f, 0.f);
            #pragma unroll
            for (int ks = 0; ks < 8; ++ks) {
                const int k0 = ks * 16;
                uint32_t af[2][4];
                ldsm4(af[0], qs_b + (uint32_t)(((wr + lrow) * SQ + k0 + lcolA) * 2));
                ldsm4(af[1], qs_b + (uint32_t)(((wr + 16 + lrow) * SQ + k0 + lcolA) * 2));
                #pragma unroll
                for (int p = 0; p < 4; ++p) {
                    uint32_t bf[4];
                    ldsm4(bf, kb + (uint32_t)(((p * 16 + brow) * SQ + k0 + bcol) * 2));
                    #pragma unroll
                    for (int mf = 0; mf < 2; ++mf) {
                        mma16(s[mf][2 * p],     af[mf], bf);
                        mma16(s[mf][2 * p + 1], af[mf], bf + 2);
                    }
                }
            }

            // ---- softmax: p = 2^s ----
            uint32_t pf[2][8][2];
            if (kt * 64 + 63 > rmin) {
                // diagonal tile: scalar mask + ex2.f32
                #pragma unroll
                for (int mf = 0; mf < 2; ++mf) {
                    const int r0 = qr0 + mf * 16, r1 = r0 + 8;
                    #pragma unroll
                    for (int nf = 0; nf < 8; ++nf) {
                        int c = kt * 64 + nf * 8 + 2 * gc;
                        float4 sv = s[mf][nf];
                        float e0 = (c     <= r0) ? ex2f(sv.x) : 0.f;
                        float e1 = (c + 1 <= r0) ? ex2f(sv.y) : 0.f;
                        float e2 = (c     <= r1) ? ex2f(sv.z) : 0.f;
                        float e3 = (c + 1 <= r1) ? ex2f(sv.w) : 0.f;
                        pf[mf][nf][0] = packh2(e0, e1);
                        pf[mf][nf][1] = packh2(e2, e3);
                    }
                }
            } else {
                // interior: pack to f16x2 first, one MUFU per pair
                #pragma unroll
                for (int mf = 0; mf < 2; ++mf)
                    #pragma unroll
                    for (int nf = 0; nf < 8; ++nf) {
                        float4 sv = s[mf][nf];
                        pf[mf][nf][0] = ex2h2(packh2(sv.x, sv.y));
                        pf[mf][nf][1] = ex2h2(packh2(sv.z, sv.w));
                    }
            }

            // ---- O += P V ; l += P 1 ----
            #pragma unroll
            for (int ks = 0; ks < 4; ++ks) {
                uint32_t pa[2][4];
                #pragma unroll
                for (int mf = 0; mf < 2; ++mf) {
                    pa[mf][0] = pf[mf][2 * ks][0];     pa[mf][1] = pf[mf][2 * ks][1];
                    pa[mf][2] = pf[mf][2 * ks + 1][0]; pa[mf][3] = pf[mf][2 * ks + 1][1];
                    mma16(lacc[mf], pa[mf], ones);
                }
                #pragma unroll
                for (int p = 0; p < 8; ++p) {
                    int n0 = p * 16;
                    uint32_t vb[4];
                    ldsm4t(vb, vb_base + (uint32_t)(((ks * 16 + lrow) * SQ + n0 + lcolA) * 2));
                    #pragma unroll
                    for (int mf = 0; mf < 2; ++mf) {
                        mma16(oacc[mf][2 * p],     pa[mf], vb);
                        mma16(oacc[mf][2 * p + 1], pa[mf], vb + 2);
                    }
                }
            }
        }
        __syncthreads();
        buf ^= 1;
    }
    cp_wait<0>();

    // ---- write unnormalized partials (l rows from lacc: .x row gr, .z row gr+8) ----
    float* Op = g_Op4[part];
    float* lp = g_lp4[part];
    #pragma unroll
    for (int mf = 0; mf < 2; ++mf) {
        const size_t r0 = (size_t)b * SEQ + qt * 128 + wr + mf * 16 + gr;
        #pragma unroll
        for (int nf = 0; nf < 16; ++nf) {
            int col = nf * 8 + 2 * gc;
            float4 v = oacc[mf][nf];
            *(float2*)&Op[r0 * HD + col]       = make_float2(v.x, v.y);
            *(float2*)&Op[(r0 + 8) * HD + col] = make_float2(v.z, v.w);
        }
        if (gc == 0) {
            lp[r0]     = lacc[mf].x;
            lp[r0 + 8] = lacc[mf].z;
        }
    }
}

// ---------------------------------------------------------------------------
__global__ __launch_bounds__(256)
void combine_kernel(float* __restrict__ out)
{
    int idx0 = blockIdx.x * 1024 + threadIdx.x;   // over 16384*32 float4, 4 per thread
    #pragma unroll
    for (int j = 0; j < 4; ++j) {
        int idx = idx0 + j * 256;
        int row = idx >> 5;
        float l0 = g_lp4[0][row], l1 = g_lp4[1][row];
        float l2 = g_lp4[2][row], l3 = g_lp4[3][row];
        float4 a = ((const float4*)g_Op4[0])[idx];
        float4 c = ((const float4*)g_Op4[1])[idx];
        float4 d = ((const float4*)g_Op4[2])[idx];
        float4 e = ((const float4*)g_Op4[3])[idx];
        float inv = 1.f / (l0 + l1 + l2 + l3);
        ((float4*)out)[idx] = make_float4((a.x + c.x + d.x + e.x) * inv,
                                          (a.y + c.y + d.y + e.y) * inv,
                                          (a.z + c.z + d.z + e.z) * inv,
                                          (a.w + c.w + d.w + e.w) * inv);
    }
}

// ---------------------------------------------------------------------------
extern "C" void kernel_launch(void* const* d_in, const int* in_sizes, int n_in,
                              void* d_out, int out_size)
{
    const float* x  = (const float*)d_in[0];
    const float* Wq = (const float*)d_in[1];
    const float* Wk = (const float*)d_in[2];
    const float* Wv = (const float*)d_in[3];
    float* out = (float*)d_out;

    cudaFuncSetAttribute(qkv_mma, cudaFuncAttributeMaxDynamicSharedMemorySize, PROJ_SMEM);
    cudaFuncSetAttribute(attn_mma, cudaFuncAttributeMaxDynamicSharedMemorySize, ATT_SMEM);

    qkv_mma<<<dim3(128, 3), 256, PROJ_SMEM>>>(x, Wq, Wk, Wv);
    attn_mma<<<dim3(4 * NQT, BATCH), 128, ATT_SMEM>>>();
    combine_kernel<<<(BATCH * SEQ * HD / 4) / 1024, 256>>>(out);
}